// round 14
// baseline (speedup 1.0000x reference)
#include <cuda_runtime.h>
#include <cfloat>

#define POOL 7
#define SCALE 0.0625f
#define BATCH 4
#define CHANS 256
#define FH 224
#define FW 224
#define FHW (FH * FW)
#define N_ROIS 512

// Channel-last scratch: [b][h][w][c], 4*224*224*256 floats = 205.5 MB
__device__ float g_T[(size_t)BATCH * FHW * CHANS];

// Replicate XLA-GPU's fp32 division (approximate, NOT correctly rounded).
// This exact op is what makes rel_err == 0 vs the reference. DO NOT CHANGE.
__device__ __forceinline__ float div_full(float a, float b) {
    float r; asm("div.full.f32 %0, %1, %2;" : "=f"(r) : "f"(a), "f"(b)); return r;
}
// round_half_up(v * 0.0625) — exact in fp32 for the input range
__device__ __forceinline__ int rhus(float v) {
    return (int)floorf(__fadd_rn(__fmul_rn(v, SCALE), 0.5f));
}
__device__ __forceinline__ float4 fmax4(float4 a, float4 b) {
    return make_float4(fmaxf(a.x, b.x), fmaxf(a.y, b.y),
                       fmaxf(a.z, b.z), fmaxf(a.w, b.w));
}

// ---------------- Kernel 1: NCHW -> NHWC transpose (exact copy) ----------
// Per batch: M[256][50176] -> T[50176][256]. 32x32 tiles via padded SMEM.
__global__ void __launch_bounds__(256) transpose_kernel(const float* __restrict__ feat) {
    __shared__ float tile[32][33];
    const int b   = blockIdx.z;
    const int hw0 = blockIdx.x << 5;          // 50176/32 = 1568 exact
    const int c0  = blockIdx.y << 5;          // 256/32 = 8 exact
    const int tx = threadIdx.x, ty = threadIdx.y;   // (32,8)

    const float* src = feat + (size_t)b * CHANS * FHW;
    #pragma unroll
    for (int j = 0; j < 4; ++j)
        tile[ty + 8 * j][tx] = src[(size_t)(c0 + ty + 8 * j) * FHW + hw0 + tx];
    __syncthreads();
    float* dst = g_T + (size_t)b * FHW * CHANS;
    #pragma unroll
    for (int j = 0; j < 4; ++j)
        dst[(size_t)(hw0 + ty + 8 * j) * CHANS + c0 + tx] = tile[tx][ty + 8 * j];
}

// ---------------- Kernel 2: channel-last ROI max-pool ---------------------
// block = (roi n = blockIdx.x, blockIdx.y = chunk*4 + binGroup), 4 warps.
// warp slot = binGroup*4 + warp handles bins slot, slot+16, slot+32.
// Lane: half = lane>>4 selects pixel (2 px/iter), lc = lane&15 -> 4 channels.
__global__ void __launch_bounds__(128) roipool_cl_kernel(
    const float* __restrict__ rois,
    float* __restrict__ out)
{
    const int warp = threadIdx.x >> 5;
    const int lane = threadIdx.x & 31;
    const int n    = blockIdx.x;
    const int chunk = blockIdx.y >> 2;           // 0..3 (slowest -> L2 phasing)
    const int bg    = blockIdx.y & 3;
    const int slot  = (bg << 2) + warp;          // 0..15
    const int c0    = chunk << 6;                // 64-channel chunk
    const int half  = lane >> 4;
    const int lc    = lane & 15;

    const float* roi = rois + n * 5;
    const int b  = (int)roi[0];
    const int xs = rhus(roi[1]);
    const int ys = rhus(roi[2]);
    const int xe = rhus(roi[3]);
    const int ye = rhus(roi[4]);
    const int roi_w = max(xe - xs + 1, 1);
    const int roi_h = max(ye - ys + 1, 1);
    const float bin_h = div_full((float)roi_h, 7.0f);
    const float bin_w = div_full((float)roi_w, 7.0f);

    const float* base = g_T + (size_t)b * FHW * CHANS + c0 + (lc << 2);
    const float NEG = -FLT_MAX;

    for (int bin = slot; bin < POOL * POOL; bin += 16) {
        const int ph = bin / POOL;
        const int pw = bin - ph * POOL;

        // Exact reference bin bounds (div.full + IEEE mul + floor/ceil + clip)
        const int hs = min(max((int)floorf(__fmul_rn((float)ph,       bin_h)) + ys, 0), FH);
        const int he = min(max((int)ceilf (__fmul_rn((float)(ph + 1), bin_h)) + ys, 0), FH);
        const int ws = min(max((int)floorf(__fmul_rn((float)pw,       bin_w)) + xs, 0), FW);
        const int we = min(max((int)ceilf (__fmul_rn((float)(pw + 1), bin_w)) + xs, 0), FW);
        const bool valid = (hs < he) && (ws < we);   // warp-uniform

        float4 acc = make_float4(NEG, NEG, NEG, NEG);
        if (valid) {
            for (int h = hs; h < he; ++h) {
                // half-warp 0 takes w, half-warp 1 takes w+1; step 2
                const float* p = base + (size_t)(h * FW + ws + half) * CHANS;
                for (int w = ws + half; w < we; w += 2, p += 2 * CHANS)
                    acc = fmax4(acc, __ldg((const float4*)p));
            }
            // merge the two pixel-halves (lane L <-> L^16 hold same channels)
            acc.x = fmaxf(acc.x, __shfl_xor_sync(0xffffffffu, acc.x, 16));
            acc.y = fmaxf(acc.y, __shfl_xor_sync(0xffffffffu, acc.y, 16));
            acc.z = fmaxf(acc.z, __shfl_xor_sync(0xffffffffu, acc.z, 16));
            acc.w = fmaxf(acc.w, __shfl_xor_sync(0xffffffffu, acc.w, 16));
        } else {
            acc = make_float4(0.0f, 0.0f, 0.0f, 0.0f);
        }

        if (lane < 16) {
            // out[n][c][ph][pw]; channel stride = 49
            const int oidx = (n * CHANS + c0 + (lc << 2)) * (POOL * POOL) + ph * POOL + pw;
            out[oidx]                       = acc.x;
            out[oidx + POOL * POOL]         = acc.y;
            out[oidx + 2 * POOL * POOL]     = acc.z;
            out[oidx + 3 * POOL * POOL]     = acc.w;
        }
    }
}

extern "C" void kernel_launch(void* const* d_in, const int* in_sizes, int n_in,
                              void* d_out, int out_size) {
    const float* feat;
    const float* rois;
    if (in_sizes[0] > in_sizes[1]) {
        feat = (const float*)d_in[0];
        rois = (const float*)d_in[1];
    } else {
        feat = (const float*)d_in[1];
        rois = (const float*)d_in[0];
    }
    float* out = (float*)d_out;

    dim3 tgrid(FHW / 32, CHANS / 32, BATCH);     // 1568 x 8 x 4
    transpose_kernel<<<tgrid, dim3(32, 8)>>>(feat);

    dim3 pgrid(N_ROIS, 16);                      // 512 x (4 chunks * 4 bin-groups)
    roipool_cl_kernel<<<pgrid, 128>>>(rois, out);
}

// round 15
// speedup vs baseline: 1.5942x; 1.5942x over previous
#include <cuda_runtime.h>
#include <cfloat>

#define POOL 7
#define SCALE 0.0625f
#define BATCH 4
#define CHANS 256
#define FH 224
#define FW 224
#define FHW (FH * FW)
#define N_ROIS 512
#define ROWSTR ((size_t)FW * CHANS)   // floats per feature row in NHWC

// Channel-last scratch: [b][h][w][c], 4*224*224*256 floats = 205.5 MB
__device__ float g_T[(size_t)BATCH * FHW * CHANS];

// Replicate XLA-GPU's fp32 division (approximate, NOT correctly rounded).
// This exact op is what makes rel_err == 0 vs the reference. DO NOT CHANGE.
__device__ __forceinline__ float div_full(float a, float b) {
    float r; asm("div.full.f32 %0, %1, %2;" : "=f"(r) : "f"(a), "f"(b)); return r;
}
// round_half_up(v * 0.0625) — exact in fp32 for the input range
__device__ __forceinline__ int rhus(float v) {
    return (int)floorf(__fadd_rn(__fmul_rn(v, SCALE), 0.5f));
}
__device__ __forceinline__ float4 fmax4(float4 a, float4 b) {
    return make_float4(fmaxf(a.x, b.x), fmaxf(a.y, b.y),
                       fmaxf(a.z, b.z), fmaxf(a.w, b.w));
}

// ---------------- Kernel 1: NCHW -> NHWC transpose (exact copy) ----------
__global__ void __launch_bounds__(256) transpose_kernel(const float* __restrict__ feat) {
    __shared__ float tile[32][33];
    const int b   = blockIdx.z;
    const int hw0 = blockIdx.x << 5;
    const int c0  = blockIdx.y << 5;
    const int tx = threadIdx.x, ty = threadIdx.y;   // (32,8)

    const float* src = feat + (size_t)b * CHANS * FHW;
    #pragma unroll
    for (int j = 0; j < 4; ++j)
        tile[ty + 8 * j][tx] = src[(size_t)(c0 + ty + 8 * j) * FHW + hw0 + tx];
    __syncthreads();
    float* dst = g_T + (size_t)b * FHW * CHANS;
    #pragma unroll
    for (int j = 0; j < 4; ++j)
        dst[(size_t)(hw0 + ty + 8 * j) * CHANS + c0 + tx] = tile[tx][ty + 8 * j];
}

// ---------------- Kernel 2: channel-last ROI max-pool ---------------------
// block = (roi n, chunk*4 + binGroup), 4 warps; warp handles 3-4 bins.
// Lane: half = lane>>4 -> pixel parity (2 px/iter), lc = lane&15 -> 4 ch.
// Mainloop: 4-row unroll x 4 independent accumulators -> 4 LDG.128 in
// flight per half-warp (latency cover; R14 had ~1 and sat idle at 32% issue).
__global__ void __launch_bounds__(128) roipool_cl_kernel(
    const float* __restrict__ rois,
    float* __restrict__ out)
{
    const int warp = threadIdx.x >> 5;
    const int lane = threadIdx.x & 31;
    const int n    = blockIdx.x;
    const int chunk = blockIdx.y >> 2;           // slowest -> L2-resident 51MB slice
    const int bg    = blockIdx.y & 3;
    const int slot  = (bg << 2) + warp;          // 0..15
    const int c0    = chunk << 6;                // 64-channel chunk
    const int half  = lane >> 4;
    const int lc    = lane & 15;

    const float* roi = rois + n * 5;
    const int b  = (int)roi[0];
    const int xs = rhus(roi[1]);
    const int ys = rhus(roi[2]);
    const int xe = rhus(roi[3]);
    const int ye = rhus(roi[4]);
    const int roi_w = max(xe - xs + 1, 1);
    const int roi_h = max(ye - ys + 1, 1);
    const float bin_h = div_full((float)roi_h, 7.0f);
    const float bin_w = div_full((float)roi_w, 7.0f);

    const float* base = g_T + (size_t)b * FHW * CHANS + c0 + (lc << 2);
    const float NEG = -FLT_MAX;

    for (int bin = slot; bin < POOL * POOL; bin += 16) {
        const int ph = bin / POOL;
        const int pw = bin - ph * POOL;

        // Exact reference bin bounds (div.full + IEEE mul + floor/ceil + clip)
        const int hs = min(max((int)floorf(__fmul_rn((float)ph,       bin_h)) + ys, 0), FH);
        const int he = min(max((int)ceilf (__fmul_rn((float)(ph + 1), bin_h)) + ys, 0), FH);
        const int ws = min(max((int)floorf(__fmul_rn((float)pw,       bin_w)) + xs, 0), FW);
        const int we = min(max((int)ceilf (__fmul_rn((float)(pw + 1), bin_w)) + xs, 0), FW);
        const bool valid = (hs < he) && (ws < we);   // warp-uniform

        float4 acc0 = make_float4(NEG, NEG, NEG, NEG);
        float4 acc1 = acc0, acc2 = acc0, acc3 = acc0;
        if (valid) {
            int h = hs;
            // 4-row unroll: 4 independent load streams per half-warp
            for (; h + 3 < he; h += 4) {
                const float* p = base + (size_t)(h * FW + ws + half) * CHANS;
                for (int w = ws + half; w < we; w += 2, p += 2 * CHANS) {
                    acc0 = fmax4(acc0, __ldg((const float4*)p));
                    acc1 = fmax4(acc1, __ldg((const float4*)(p + ROWSTR)));
                    acc2 = fmax4(acc2, __ldg((const float4*)(p + 2 * ROWSTR)));
                    acc3 = fmax4(acc3, __ldg((const float4*)(p + 3 * ROWSTR)));
                }
            }
            // tail rows (0..3): round-robin into the 4 accumulators
            for (int t = 0; h < he; ++h, ++t) {
                const float* p = base + (size_t)(h * FW + ws + half) * CHANS;
                float4 a = make_float4(NEG, NEG, NEG, NEG);
                for (int w = ws + half; w < we; w += 2, p += 2 * CHANS)
                    a = fmax4(a, __ldg((const float4*)p));
                if (t == 0) acc0 = fmax4(acc0, a);
                else if (t == 1) acc1 = fmax4(acc1, a);
                else acc2 = fmax4(acc2, a);
            }
            acc0 = fmax4(fmax4(acc0, acc1), fmax4(acc2, acc3));
            // merge the two pixel-halves (lane L <-> L^16 hold same channels)
            acc0.x = fmaxf(acc0.x, __shfl_xor_sync(0xffffffffu, acc0.x, 16));
            acc0.y = fmaxf(acc0.y, __shfl_xor_sync(0xffffffffu, acc0.y, 16));
            acc0.z = fmaxf(acc0.z, __shfl_xor_sync(0xffffffffu, acc0.z, 16));
            acc0.w = fmaxf(acc0.w, __shfl_xor_sync(0xffffffffu, acc0.w, 16));
        } else {
            acc0 = make_float4(0.0f, 0.0f, 0.0f, 0.0f);
        }

        if (lane < 16) {
            // out[n][c][ph][pw]; channel stride = 49
            const int oidx = (n * CHANS + c0 + (lc << 2)) * (POOL * POOL) + ph * POOL + pw;
            out[oidx]                   = acc0.x;
            out[oidx + POOL * POOL]     = acc0.y;
            out[oidx + 2 * POOL * POOL] = acc0.z;
            out[oidx + 3 * POOL * POOL] = acc0.w;
        }
    }
}

extern "C" void kernel_launch(void* const* d_in, const int* in_sizes, int n_in,
                              void* d_out, int out_size) {
    const float* feat;
    const float* rois;
    if (in_sizes[0] > in_sizes[1]) {
        feat = (const float*)d_in[0];
        rois = (const float*)d_in[1];
    } else {
        feat = (const float*)d_in[1];
        rois = (const float*)d_in[0];
    }
    float* out = (float*)d_out;

    dim3 tgrid(FHW / 32, CHANS / 32, BATCH);     // 1568 x 8 x 4
    transpose_kernel<<<tgrid, dim3(32, 8)>>>(feat);

    dim3 pgrid(N_ROIS, 16);                      // 512 x (4 chunks * 4 bin-groups)
    roipool_cl_kernel<<<pgrid, 128>>>(rois, out);
}